// round 15
// baseline (speedup 1.0000x reference)
#include <cuda_runtime.h>
#include <cstdint>

// Problem constants
#define B_TOTAL 4096
#define T_STEPS 1024
#define HID     64
#define GATES3  192              // 3*HID
#define NB      7                // batch elements per PAIR of warps
#define PAIRS   4                // pairs per CTA
#define WARPS   (PAIRS * 2)      // 8 warps -> 2 per SMSP
#define THREADS (WARPS * 32)     // 256
#define BPC     (PAIRS * NB)     // 28 batches per CTA
#define CTAS    ((B_TOTAL + BPC - 1) / BPC)   // 147
#define QREG    6                // own-half k-quads cached in registers

// packed fp32x2 FMA (Blackwell FFMA2 — 2 MACs per lane-op)
__device__ __forceinline__ unsigned long long ffma2(unsigned long long a,
                                                    unsigned long long b,
                                                    unsigned long long c) {
    unsigned long long d;
    asm("fma.rn.f32x2 %0, %1, %2, %3;" : "=l"(d) : "l"(a), "l"(b), "l"(c));
    return d;
}
__device__ __forceinline__ float lo32(unsigned long long v) {
    return __uint_as_float((unsigned)v);
}
__device__ __forceinline__ float hi32(unsigned long long v) {
    return __uint_as_float((unsigned)(v >> 32));
}
__device__ __forceinline__ unsigned long long pack2(float lo, float hi) {
    return ((unsigned long long)__float_as_uint(hi) << 32) | __float_as_uint(lo);
}

// Hardware tanh (single MUFU op)
__device__ __forceinline__ float tanh_hw(float v) {
    float r;
    asm("tanh.approx.f32 %0, %1;" : "=f"(r) : "f"(v));
    return r;
}
__device__ __forceinline__ float lrelu(float v) {
    return v > 0.0f ? v : 0.01f * v;
}

__global__ __launch_bounds__(THREADS, 1)
void gru_fused(const float* __restrict__ x,
               const float* __restrict__ wih_g, const float* __restrict__ whh_g,
               const float* __restrict__ bih_g, const float* __restrict__ bhh_g,
               const float* __restrict__ w1, const float* __restrict__ b1,
               const float* __restrict__ w2, const float* __restrict__ b2,
               const float* __restrict__ w3, const float* __restrict__ b3,
               float* __restrict__ out)
{
    extern __shared__ float smem[];
    // Wq layout: [16 k-quads][192 rows] of float4: Wq[q][row] = W[row][4q..4q+3]
    // r/z rows (0..127) PRE-SCALED by 0.5: sigmoid(v) = 0.5*tanh(0.5v)+0.5.
    float* wq  = smem;                            // 16*192*4 floats = 48KB
    float* h_s = smem + 16 * GATES3 * 4;          // [PAIRS][2][NB][HID]

    const int tid  = threadIdx.x;
    const int w    = tid >> 5;
    const int l    = tid & 31;
    // Pair partners on ADJACENT SMSPs; each SMSP hosts warps from two
    // INDEPENDENT pairs so barrier phases drift and tails overlap FFMAs.
    const int pair = w >> 1;       // 0..3
    const int half = w & 1;        // 0: h[0:32), 1: h[32:64)

    // Own-half k-quad range: this warp WRITES h[half*32 .. half*32+31], i.e.
    // exactly the h values consumed by quads [half*8, half*8+8). Those can be
    // processed right after __syncwarp, BEFORE the pair barrier.
    const int qown = half * 8;     // own-half base quad
    const int qoth = 8 - qown;     // partner-half base quad

    // Stage W_hh transposed into smem; scale r/z rows by 0.5.
    {
        const float4* whh4 = (const float4*)whh_g;
        float4* wq4 = (float4*)wq;
        for (int i = tid; i < GATES3 * 16; i += THREADS) {
            const int row = i >> 4;
            const int q = i & 15;
            float4 v = whh4[i];
            if (row < 2 * HID) { v.x *= 0.5f; v.y *= 0.5f; v.z *= 0.5f; v.w *= 0.5f; }
            wq4[q * GATES3 + row] = v;
        }
    }

    // Zero both h buffers for this pair (h0 = 0)
    float* hp = h_s + pair * (2 * NB * HID);
    for (int i = half * 32 + l; i < 2 * NB * HID; i += 64) hp[i] = 0.0f;

    __syncthreads();

    const int b0 = blockIdx.x * BPC + pair * NB;
    const int hidx = l + 32 * half;   // the h index this lane owns
    const int barid = pair + 1;       // named barrier per pair (64 threads)

    // Per-lane params. r/z: wih and (bih+bhh) pre-scaled by 0.5 (full gi fold).
    // n: bhh stays in acc (scaled by r); gi_n = wih*x + bih applied in tail.
    float wih05[2], bihh05[2], wih_n, bih_n, bhh_n;
    int wrow[3];
#pragma unroll
    for (int g = 0; g < 3; ++g) {
        const int row = g * HID + hidx;
        wrow[g] = row * 4;
        if (g < 2) {
            wih05[g]  = 0.5f * __ldg(&wih_g[row]);
            bihh05[g] = 0.5f * (__ldg(&bih_g[row]) + __ldg(&bhh_g[row]));
        } else {
            wih_n = __ldg(&wih_g[row]);
            bih_n = __ldg(&bih_g[row]);
            bhh_n = __ldg(&bhh_g[row]);
        }
    }

    // Register-cache the first QREG quads of this warp's OWN half
    // (compile-time indices -> stays in registers).
    ulonglong2 wreg[3][QREG];
#pragma unroll
    for (int g = 0; g < 3; ++g)
#pragma unroll
        for (int qq = 0; qq < QREG; ++qq)
            wreg[g][qq] = *(const ulonglong2*)(wq + (qown + qq) * (GATES3 * 4) + wrow[g]);

    const float* xrow[NB];
#pragma unroll
    for (int b = 0; b < NB; ++b) {
        int bb = b0 + b;
        if (bb >= B_TOTAL) bb = B_TOTAL - 1;   // tail CTA: clamp (results discarded)
        xrow[b] = x + (size_t)bb * T_STEPS;
    }

    float hreg[NB];                   // this lane's own h values
    float xcur[NB], xnxt[NB];
#pragma unroll
    for (int b = 0; b < NB; ++b) {
        hreg[b] = 0.0f;
        xcur[b] = __ldg(&xrow[b][0]);
    }

    // ---------------- recurrence ----------------
    for (int t = 0; t < T_STEPS; ++t) {
        const float* hc = hp + (t & 1) * (NB * HID);
        float*       hn = hp + ((t + 1) & 1) * (NB * HID);

        // Prefetch x for next step
        const int tn = (t + 1) & (T_STEPS - 1);
#pragma unroll
        for (int b = 0; b < NB; ++b) xnxt[b] = __ldg(&xrow[b][tn]);

        // Packed accumulators. r/z: lo-init = full scaled gi; n: lo-init = bhh_n.
        unsigned long long acc[NB][3];
#pragma unroll
        for (int b = 0; b < NB; ++b) {
            acc[b][0] = pack2(fmaf(wih05[0], xcur[b], bihh05[0]), 0.0f);
            acc[b][1] = pack2(fmaf(wih05[1], xcur[b], bihh05[1]), 0.0f);
            acc[b][2] = pack2(bhh_n, 0.0f);
        }

        // ---- phase 1: OWN half (q = qown..qown+7) — no cross-warp sync needed.
        // These h values were stored by THIS warp last step (visible after
        // __syncwarp); ~770 cyc of runway that absorbs partner skew + tail.
#pragma unroll
        for (int qi = 0; qi < 8; ++qi) {
            const int q = qown + qi;
            ulonglong2 hv[NB];
#pragma unroll
            for (int b = 0; b < NB; ++b)
                hv[b] = *(const ulonglong2*)(hc + b * HID + q * 4);

            ulonglong2 wv[3];
            if (qi < QREG) {
#pragma unroll
                for (int g = 0; g < 3; ++g) wv[g] = wreg[g][qi];
            } else {
                const float* wqq = wq + q * (GATES3 * 4);
#pragma unroll
                for (int g = 0; g < 3; ++g)
                    wv[g] = *(const ulonglong2*)(wqq + wrow[g]);
            }

#pragma unroll
            for (int g = 0; g < 3; ++g) {
#pragma unroll
                for (int b = 0; b < NB; ++b) {
                    acc[b][g] = ffma2(wv[g].x, hv[b].x, acc[b][g]);
                    acc[b][g] = ffma2(wv[g].y, hv[b].y, acc[b][g]);
                }
            }
        }

        // Pair barrier: partner's h(t) half now visible (bar.sync drains STS).
        asm volatile("bar.sync %0, %1;" :: "r"(barid), "r"(64) : "memory");

        // ---- phase 2: PARTNER half (q = qoth..qoth+7), weights from smem.
#pragma unroll
        for (int qi = 0; qi < 8; ++qi) {
            const int q = qoth + qi;
            ulonglong2 hv[NB];
#pragma unroll
            for (int b = 0; b < NB; ++b)
                hv[b] = *(const ulonglong2*)(hc + b * HID + q * 4);

            const float* wqq = wq + q * (GATES3 * 4);
            ulonglong2 wv[3];
#pragma unroll
            for (int g = 0; g < 3; ++g)
                wv[g] = *(const ulonglong2*)(wqq + wrow[g]);

#pragma unroll
            for (int g = 0; g < 3; ++g) {
#pragma unroll
                for (int b = 0; b < NB; ++b) {
                    acc[b][g] = ffma2(wv[g].x, hv[b].x, acc[b][g]);
                    acc[b][g] = ffma2(wv[g].y, hv[b].y, acc[b][g]);
                }
            }
        }

        // Gates + state update. r/z tail: FADD -> MUFU -> FMA.
#pragma unroll
        for (int b = 0; b < NB; ++b) {
            const float rv = fmaf(0.5f, tanh_hw(lo32(acc[b][0]) + hi32(acc[b][0])), 0.5f);
            const float zv = fmaf(0.5f, tanh_hw(lo32(acc[b][1]) + hi32(acc[b][1])), 0.5f);
            const float ghn = lo32(acc[b][2]) + hi32(acc[b][2]);   // h-proj + bhh_n
            const float gin = fmaf(wih_n, xcur[b], bih_n);         // x-proj + bih_n
            const float nv  = tanh_hw(fmaf(rv, ghn, gin));

            const float hnew = nv + zv * (hreg[b] - nv);
            hreg[b] = hnew;
            hn[b * HID + hidx] = hnew;
            xcur[b] = xnxt[b];
        }
        // Own stores visible to own warp next step; partner sees them after
        // the mid-step bar.sync of step t+1.
        __syncwarp();
    }

    // Final pair barrier: both halves of h(T) visible before the head reads.
    asm volatile("bar.sync %0, %1;" :: "r"(barid), "r"(64) : "memory");

    // ---------------- MLP head: 64 -> 32 -> 16 -> 1 ----------------
    // T even => final h is in buffer 0; buffer 1 is free scratch.
    const float* hf  = hp;                          // [NB][HID]
    float*       scr = hp + NB * HID + half * 32;   // 32 floats per warp

    // Each warp of the pair handles alternating batches.
#pragma unroll
    for (int b = 0; b < NB; ++b) {
        if ((b & 1) != half) continue;
        const float* hb = hf + b * HID;

        // layer 1: each lane computes one of 32 outputs
        float a1 = __ldg(&b1[l]);
#pragma unroll 8
        for (int k = 0; k < HID; ++k)
            a1 = fmaf(__ldg(&w1[l * HID + k]), hb[k], a1);
        scr[l] = lrelu(a1);
        __syncwarp();

        // layer 2 (lanes 0..15) + layer 3 partials
        float part = 0.0f;
        if (l < 16) {
            float a2 = __ldg(&b2[l]);
#pragma unroll
            for (int k = 0; k < 32; ++k)
                a2 = fmaf(__ldg(&w2[l * 32 + k]), scr[k], a2);
            part = __ldg(&w3[l]) * lrelu(a2);
        }
#pragma unroll
        for (int off = 8; off; off >>= 1)
            part += __shfl_down_sync(0xffffffffu, part, off);
        if (l == 0 && b0 + b < B_TOTAL) out[b0 + b] = part + __ldg(&b3[0]);
        __syncwarp();
    }
}

extern "C" void kernel_launch(void* const* d_in, const int* in_sizes, int n_in,
                              void* d_out, int out_size)
{
    const float* x     = (const float*)d_in[0];
    const float* wih   = (const float*)d_in[1];
    const float* whh   = (const float*)d_in[2];
    const float* bih   = (const float*)d_in[3];
    const float* bhh   = (const float*)d_in[4];
    const float* w1    = (const float*)d_in[5];
    const float* b1    = (const float*)d_in[6];
    const float* w2    = (const float*)d_in[7];
    const float* b2    = (const float*)d_in[8];
    const float* w3    = (const float*)d_in[9];
    const float* b3    = (const float*)d_in[10];
    float* out = (float*)d_out;

    const int smem_bytes = (16 * GATES3 * 4 + PAIRS * 2 * NB * HID) * (int)sizeof(float);
    cudaFuncSetAttribute(gru_fused, cudaFuncAttributeMaxDynamicSharedMemorySize, smem_bytes);

    gru_fused<<<CTAS, THREADS, smem_bytes>>>(x, wih, whh, bih, bhh,
                                             w1, b1, w2, b2, w3, b3, out);
}

// round 16
// speedup vs baseline: 1.0242x; 1.0242x over previous
#include <cuda_runtime.h>
#include <cstdint>

// Problem constants
#define B_TOTAL 4096
#define T_STEPS 1024
#define HID     64
#define GATES3  192              // 3*HID
#define NB      7                // batch elements per PAIR of warps
#define PAIRS   4                // pairs per CTA
#define WARPS   (PAIRS * 2)      // 8 warps -> 2 per SMSP
#define THREADS (WARPS * 32)     // 256
#define BPC     (PAIRS * NB)     // 28 batches per CTA
#define CTAS    ((B_TOTAL + BPC - 1) / BPC)   // 147
#define QREG    6                // own-half k-quads cached in registers

// packed fp32x2 FMA (Blackwell FFMA2 — 2 MACs per lane-op)
__device__ __forceinline__ unsigned long long ffma2(unsigned long long a,
                                                    unsigned long long b,
                                                    unsigned long long c) {
    unsigned long long d;
    asm("fma.rn.f32x2 %0, %1, %2, %3;" : "=l"(d) : "l"(a), "l"(b), "l"(c));
    return d;
}
__device__ __forceinline__ float lo32(unsigned long long v) {
    return __uint_as_float((unsigned)v);
}
__device__ __forceinline__ float hi32(unsigned long long v) {
    return __uint_as_float((unsigned)(v >> 32));
}
__device__ __forceinline__ unsigned long long pack2(float lo, float hi) {
    return ((unsigned long long)__float_as_uint(hi) << 32) | __float_as_uint(lo);
}

// Hardware tanh (single MUFU op)
__device__ __forceinline__ float tanh_hw(float v) {
    float r;
    asm("tanh.approx.f32 %0, %1;" : "=f"(r) : "f"(v));
    return r;
}
__device__ __forceinline__ float lrelu(float v) {
    return v > 0.0f ? v : 0.01f * v;
}

__global__ __launch_bounds__(THREADS, 1)
void gru_fused(const float* __restrict__ x,
               const float* __restrict__ wih_g, const float* __restrict__ whh_g,
               const float* __restrict__ bih_g, const float* __restrict__ bhh_g,
               const float* __restrict__ w1, const float* __restrict__ b1,
               const float* __restrict__ w2, const float* __restrict__ b2,
               const float* __restrict__ w3, const float* __restrict__ b3,
               float* __restrict__ out)
{
    extern __shared__ float smem[];
    // Wq layout: [16 k-quads][192 rows] of float4: Wq[q][row] = W[row][4q..4q+3]
    // r/z rows (0..127) PRE-SCALED by 0.5: sigmoid(v) = 0.5*tanh(0.5v)+0.5.
    float* wq  = smem;                            // 16*192*4 floats = 48KB
    float* h_s = smem + 16 * GATES3 * 4;          // [PAIRS][2][NB][HID]

    const int tid  = threadIdx.x;
    const int w    = tid >> 5;
    const int l    = tid & 31;
    // Pair partners on ADJACENT SMSPs; each SMSP hosts warps from two
    // INDEPENDENT pairs so barrier phases drift and tails overlap FFMAs.
    const int pair = w >> 1;       // 0..3
    const int half = w & 1;        // 0: h[0:32), 1: h[32:64)

    // Own-half quad base: quads [qown, qown+8) consume the h values THIS warp
    // wrote last step. We iterate them FIRST (post-barrier window = pure
    // h-load + FFMA2, no weight LDS) and register-cache 6 of them.
    const int qown = half * 8;
    const int qoth = 8 - qown;

    // Stage W_hh transposed into smem; scale r/z rows by 0.5.
    {
        const float4* whh4 = (const float4*)whh_g;
        float4* wq4 = (float4*)wq;
        for (int i = tid; i < GATES3 * 16; i += THREADS) {
            const int row = i >> 4;
            const int q = i & 15;
            float4 v = whh4[i];
            if (row < 2 * HID) { v.x *= 0.5f; v.y *= 0.5f; v.z *= 0.5f; v.w *= 0.5f; }
            wq4[q * GATES3 + row] = v;
        }
    }

    // Zero both h buffers for this pair (h0 = 0)
    float* hp = h_s + pair * (2 * NB * HID);
    for (int i = half * 32 + l; i < 2 * NB * HID; i += 64) hp[i] = 0.0f;

    __syncthreads();

    const int b0 = blockIdx.x * BPC + pair * NB;
    const int hidx = l + 32 * half;   // the h index this lane owns
    const int barid = pair + 1;       // named barrier per pair (64 threads)

    // Per-lane params. r/z: wih and (bih+bhh) pre-scaled by 0.5 (full gi fold).
    // n: bhh stays in acc (scaled by r); gi_n = wih*x + bih applied in tail.
    float wih05[2], bihh05[2], wih_n, bih_n, bhh_n;
    int wrow[3];
#pragma unroll
    for (int g = 0; g < 3; ++g) {
        const int row = g * HID + hidx;
        wrow[g] = row * 4;
        if (g < 2) {
            wih05[g]  = 0.5f * __ldg(&wih_g[row]);
            bihh05[g] = 0.5f * (__ldg(&bih_g[row]) + __ldg(&bhh_g[row]));
        } else {
            wih_n = __ldg(&wih_g[row]);
            bih_n = __ldg(&bih_g[row]);
            bhh_n = __ldg(&bhh_g[row]);
        }
    }

    // Register-cache the first QREG quads of this warp's OWN half
    // (compile-time indices in the unrolled loop -> stays in registers).
    ulonglong2 wreg[3][QREG];
#pragma unroll
    for (int g = 0; g < 3; ++g)
#pragma unroll
        for (int qq = 0; qq < QREG; ++qq)
            wreg[g][qq] = *(const ulonglong2*)(wq + (qown + qq) * (GATES3 * 4) + wrow[g]);

    const float* xrow[NB];
#pragma unroll
    for (int b = 0; b < NB; ++b) {
        int bb = b0 + b;
        if (bb >= B_TOTAL) bb = B_TOTAL - 1;   // tail CTA: clamp (results discarded)
        xrow[b] = x + (size_t)bb * T_STEPS;
    }

    float hreg[NB];                   // this lane's own h values
    float xcur[NB], xnxt[NB];
#pragma unroll
    for (int b = 0; b < NB; ++b) {
        hreg[b] = 0.0f;
        xcur[b] = __ldg(&xrow[b][0]);
    }

    // ---------------- recurrence ----------------
    for (int t = 0; t < T_STEPS; ++t) {
        const float* hc = hp + (t & 1) * (NB * HID);
        float*       hn = hp + ((t + 1) & 1) * (NB * HID);

        // Prefetch x for next step (consumed ~1 full step later -> hidden)
        const int tn = (t + 1) & (T_STEPS - 1);
#pragma unroll
        for (int b = 0; b < NB; ++b) xnxt[b] = __ldg(&xrow[b][tn]);

        // Packed accumulators (short lifetime: inside this iteration only).
        // r/z: lo-init = full scaled gi = 0.5*(wih*x + bih + bhh).
        // n:   lo-init = bhh_n (r scales the whole hidden projection + bhh_n).
        unsigned long long acc[NB][3];
#pragma unroll
        for (int b = 0; b < NB; ++b) {
            acc[b][0] = pack2(fmaf(wih05[0], xcur[b], bihh05[0]), 0.0f);
            acc[b][1] = pack2(fmaf(wih05[1], xcur[b], bihh05[1]), 0.0f);
            acc[b][2] = pack2(bhh_n, 0.0f);
        }

        // Fully unrolled q-loop, OWN-half quads first (qi 0..7 -> own half,
        // qi 8..15 -> partner half). First QREG iterations use the register
        // cache: no weight LDS in the post-barrier window.
#pragma unroll
        for (int qi = 0; qi < 16; ++qi) {
            const int q = (qi < 8) ? (qown + qi) : (qoth + qi - 8);

            // h quad per batch: warp-uniform address -> broadcast (1 wavefront)
            ulonglong2 hv[NB];
#pragma unroll
            for (int b = 0; b < NB; ++b)
                hv[b] = *(const ulonglong2*)(hc + b * HID + q * 4);

            ulonglong2 wv[3];
            if (qi < QREG) {
#pragma unroll
                for (int g = 0; g < 3; ++g) wv[g] = wreg[g][qi];
            } else {
                const float* wqq = wq + q * (GATES3 * 4);
#pragma unroll
                for (int g = 0; g < 3; ++g)
                    wv[g] = *(const ulonglong2*)(wqq + wrow[g]);
            }

#pragma unroll
            for (int g = 0; g < 3; ++g) {
#pragma unroll
                for (int b = 0; b < NB; ++b) {
                    acc[b][g] = ffma2(wv[g].x, hv[b].x, acc[b][g]);
                    acc[b][g] = ffma2(wv[g].y, hv[b].y, acc[b][g]);
                }
            }
        }

        // Gates + state update. r/z tail: FADD -> MUFU -> FMA.
#pragma unroll
        for (int b = 0; b < NB; ++b) {
            const float rv = fmaf(0.5f, tanh_hw(lo32(acc[b][0]) + hi32(acc[b][0])), 0.5f);
            const float zv = fmaf(0.5f, tanh_hw(lo32(acc[b][1]) + hi32(acc[b][1])), 0.5f);
            const float ghn = lo32(acc[b][2]) + hi32(acc[b][2]);   // h-proj + bhh_n
            const float gin = fmaf(wih_n, xcur[b], bih_n);         // x-proj + bih_n
            const float nv  = tanh_hw(fmaf(rv, ghn, gin));

            const float hnew = nv + zv * (hreg[b] - nv);
            hreg[b] = hnew;
            hn[b * HID + hidx] = hnew;
            xcur[b] = xnxt[b];
        }
        // Pair-local barrier (2 warps, 64 threads): publishes h halves
        asm volatile("bar.sync %0, %1;" :: "r"(barid), "r"(64) : "memory");
    }

    // ---------------- MLP head: 64 -> 32 -> 16 -> 1 ----------------
    // T even => final h is in buffer 0; buffer 1 is free scratch.
    const float* hf  = hp;                          // [NB][HID]
    float*       scr = hp + NB * HID + half * 32;   // 32 floats per warp

    // Each warp of the pair handles alternating batches.
#pragma unroll
    for (int b = 0; b < NB; ++b) {
        if ((b & 1) != half) continue;
        const float* hb = hf + b * HID;

        // layer 1: each lane computes one of 32 outputs
        float a1 = __ldg(&b1[l]);
#pragma unroll 8
        for (int k = 0; k < HID; ++k)
            a1 = fmaf(__ldg(&w1[l * HID + k]), hb[k], a1);
        scr[l] = lrelu(a1);
        __syncwarp();

        // layer 2 (lanes 0..15) + layer 3 partials
        float part = 0.0f;
        if (l < 16) {
            float a2 = __ldg(&b2[l]);
#pragma unroll
            for (int k = 0; k < 32; ++k)
                a2 = fmaf(__ldg(&w2[l * 32 + k]), scr[k], a2);
            part = __ldg(&w3[l]) * lrelu(a2);
        }
#pragma unroll
        for (int off = 8; off; off >>= 1)
            part += __shfl_down_sync(0xffffffffu, part, off);
        if (l == 0 && b0 + b < B_TOTAL) out[b0 + b] = part + __ldg(&b3[0]);
        __syncwarp();
    }
}

extern "C" void kernel_launch(void* const* d_in, const int* in_sizes, int n_in,
                              void* d_out, int out_size)
{
    const float* x     = (const float*)d_in[0];
    const float* wih   = (const float*)d_in[1];
    const float* whh   = (const float*)d_in[2];
    const float* bih   = (const float*)d_in[3];
    const float* bhh   = (const float*)d_in[4];
    const float* w1    = (const float*)d_in[5];
    const float* b1    = (const float*)d_in[6];
    const float* w2    = (const float*)d_in[7];
    const float* b2    = (const float*)d_in[8];
    const float* w3    = (const float*)d_in[9];
    const float* b3    = (const float*)d_in[10];
    float* out = (float*)d_out;

    const int smem_bytes = (16 * GATES3 * 4 + PAIRS * 2 * NB * HID) * (int)sizeof(float);
    cudaFuncSetAttribute(gru_fused, cudaFuncAttributeMaxDynamicSharedMemorySize, smem_bytes);

    gru_fused<<<CTAS, THREADS, smem_bytes>>>(x, wih, whh, bih, bhh,
                                             w1, b1, w2, b2, w3, b3, out);
}